// round 1
// baseline (speedup 1.0000x reference)
#include <cuda_runtime.h>
#include <math.h>

#define BATCH 32
#define CH    64
#define HH    256
#define WW    256
#define NCHAN (BATCH * CH)   // 2048

// Per-channel reductions: [0]=sum(x) [1]=S0 [2]=T0 [3]=S1 [4]=T1
__device__ float g_red[5 * NCHAN];

__device__ __forceinline__ void acc_elem(float mx, float mn, float y,
                                         float& S0, float& T0,
                                         float& S1, float& T1) {
    float l0 = mx - y;            // maxpool includes center -> >= 0 exactly
    float l1 = y - mn;
    S0 += l0;
    S1 += l1;
    T0 += (l0 > 0.f) ? l0 * __logf(l0) : 0.f;
    T1 += (l1 > 0.f) ? l1 * __logf(l1) : 0.f;
}

// One block per (b,c) channel. 64 threads, 4 columns each (float4).
// Horizontal 3-window max/min via one smem row buffer; vertical 3-row
// max/min via rolling registers (same thread owns same columns).
__global__ __launch_bounds__(64)
void topo_reduce_kernel(const float* __restrict__ x) {
    const int ch = blockIdx.x;
    const float* __restrict__ base = x + (size_t)ch * (HH * WW);
    const int tid = threadIdx.x;
    const int c0  = tid * 4;

    __shared__ float row[2][WW];

    const bool hasL = (c0 != 0);
    const bool hasR = (c0 + 4 != WW);

    float4 xm1 = make_float4(0.f, 0.f, 0.f, 0.f);
    float4 hxA = xm1, hxB = xm1, hxC = xm1;
    float4 hnA = xm1, hnB = xm1, hnC = xm1;

    float zacc = 0.f, S0 = 0.f, T0 = 0.f, S1 = 0.f, T1 = 0.f;

    float4 v = *(const float4*)(base + c0);   // row 0

    for (int r = 0; r < HH; ++r) {
        const int buf = r & 1;
        *(float4*)&row[buf][c0] = v;
        // prefetch next row while this one is processed
        float4 vn = v;
        if (r + 1 < HH) vn = *(const float4*)(base + (r + 1) * WW + c0);

        zacc += (v.x + v.y) + (v.z + v.w);
        __syncthreads();

        float nb_l = hasL ? row[buf][c0 - 1] : 0.f;
        float nb_r = hasR ? row[buf][c0 + 4] : 0.f;
        float lmax = hasL ? nb_l : -INFINITY;
        float rmax = hasR ? nb_r : -INFINITY;
        float lmin = hasL ? nb_l :  INFINITY;
        float rmin = hasR ? nb_r :  INFINITY;

        float4 hx, hn;
        hx.x = fmaxf(lmax, fmaxf(v.x, v.y));
        hx.y = fmaxf(v.x,  fmaxf(v.y, v.z));
        hx.z = fmaxf(v.y,  fmaxf(v.z, v.w));
        hx.w = fmaxf(fmaxf(v.z, v.w), rmax);
        hn.x = fminf(lmin, fminf(v.x, v.y));
        hn.y = fminf(v.x,  fminf(v.y, v.z));
        hn.z = fminf(v.y,  fminf(v.z, v.w));
        hn.w = fminf(fminf(v.z, v.w), rmin);

        hxA = hxB; hxB = hxC; hxC = hx;
        hnA = hnB; hnB = hnC; hnC = hn;

        if (r >= 1) {
            // finalize output row r-1: window rows (r-2), r-1, r
            float4 mx, mn;
            mx.x = fmaxf(hxB.x, hxC.x); mn.x = fminf(hnB.x, hnC.x);
            mx.y = fmaxf(hxB.y, hxC.y); mn.y = fminf(hnB.y, hnC.y);
            mx.z = fmaxf(hxB.z, hxC.z); mn.z = fminf(hnB.z, hnC.z);
            mx.w = fmaxf(hxB.w, hxC.w); mn.w = fminf(hnB.w, hnC.w);
            if (r >= 2) {
                mx.x = fmaxf(mx.x, hxA.x); mn.x = fminf(mn.x, hnA.x);
                mx.y = fmaxf(mx.y, hxA.y); mn.y = fminf(mn.y, hnA.y);
                mx.z = fmaxf(mx.z, hxA.z); mn.z = fminf(mn.z, hnA.z);
                mx.w = fmaxf(mx.w, hxA.w); mn.w = fminf(mn.w, hnA.w);
            }
            acc_elem(mx.x, mn.x, xm1.x, S0, T0, S1, T1);
            acc_elem(mx.y, mn.y, xm1.y, S0, T0, S1, T1);
            acc_elem(mx.z, mn.z, xm1.z, S0, T0, S1, T1);
            acc_elem(mx.w, mn.w, xm1.w, S0, T0, S1, T1);
        }
        xm1 = v;
        v = vn;
    }
    // final output row 255: window rows 254,255 = hxB,hxC
    {
        float4 mx, mn;
        mx.x = fmaxf(hxB.x, hxC.x); mn.x = fminf(hnB.x, hnC.x);
        mx.y = fmaxf(hxB.y, hxC.y); mn.y = fminf(hnB.y, hnC.y);
        mx.z = fmaxf(hxB.z, hxC.z); mn.z = fminf(hnB.z, hnC.z);
        mx.w = fmaxf(hxB.w, hxC.w); mn.w = fminf(hnB.w, hnC.w);
        acc_elem(mx.x, mn.x, xm1.x, S0, T0, S1, T1);
        acc_elem(mx.y, mn.y, xm1.y, S0, T0, S1, T1);
        acc_elem(mx.z, mn.z, xm1.z, S0, T0, S1, T1);
        acc_elem(mx.w, mn.w, xm1.w, S0, T0, S1, T1);
    }

    // block reduction: 2 warps
    #pragma unroll
    for (int o = 16; o; o >>= 1) {
        zacc += __shfl_down_sync(0xffffffffu, zacc, o);
        S0   += __shfl_down_sync(0xffffffffu, S0,   o);
        T0   += __shfl_down_sync(0xffffffffu, T0,   o);
        S1   += __shfl_down_sync(0xffffffffu, S1,   o);
        T1   += __shfl_down_sync(0xffffffffu, T1,   o);
    }
    __shared__ float red[5][2];
    const int lane = tid & 31, wrp = tid >> 5;
    if (lane == 0) {
        red[0][wrp] = zacc; red[1][wrp] = S0; red[2][wrp] = T0;
        red[3][wrp] = S1;   red[4][wrp] = T1;
    }
    __syncthreads();
    if (tid == 0) {
        g_red[0 * NCHAN + ch] = red[0][0] + red[0][1];
        g_red[1 * NCHAN + ch] = red[1][0] + red[1][1];
        g_red[2 * NCHAN + ch] = red[2][0] + red[2][1];
        g_red[3 * NCHAN + ch] = red[3][0] + red[3][1];
        g_red[4 * NCHAN + ch] = red[4][0] + red[4][1];
    }
}

// Single-block head: MLPs + softmax + entropy closed-form + classifier.
// Output layout: logits[32*5] | w[32*64] | f[32*2]  (tuple concat order)
__global__ __launch_bounds__(256)
void head_kernel(const float* __restrict__ fc1_w, const float* __restrict__ fc1_b,
                 const float* __restrict__ fc2_w, const float* __restrict__ fc2_b,
                 const float* __restrict__ cls1_w, const float* __restrict__ cls1_b,
                 const float* __restrict__ cls2_w, const float* __restrict__ cls2_b,
                 float* __restrict__ out) {
    const int HID = 32, MLPD = 128, NC = 5;
    __shared__ float z[NCHAN];       // [32][64]
    __shared__ float h[BATCH * 32];  // [32][32]
    __shared__ float wsm[NCHAN];     // [32][64]
    __shared__ float c0s[NCHAN];
    __shared__ float c1s[BATCH * 128];  // reused as m[32][128] later
    __shared__ float fbuf[BATCH * 2];

    const int tid = threadIdx.x;

    // channel means
    for (int i = tid; i < NCHAN; i += 256)
        z[i] = g_red[i] * (1.f / 65536.f);
    __syncthreads();

    // h = relu(z @ fc1_w^T + fc1_b)   [32,32]
    for (int i = tid; i < BATCH * HID; i += 256) {
        int b = i >> 5, j = i & 31;
        float acc = fc1_b[j];
        const float* wr = fc1_w + j * CH;
        const float* zr = z + b * CH;
        #pragma unroll 8
        for (int c = 0; c < CH; ++c) acc += zr[c] * wr[c];
        h[i] = fmaxf(acc, 0.f);
    }
    __syncthreads();

    // pre-softmax logits for w   [32,64]
    for (int i = tid; i < NCHAN; i += 256) {
        int b = i >> 6, c = i & 63;
        float acc = fc2_b[c];
        const float* wr = fc2_w + c * HID;
        const float* hr = h + b * HID;
        #pragma unroll 8
        for (int j = 0; j < HID; ++j) acc += hr[j] * wr[j];
        wsm[i] = acc;
    }
    __syncthreads();

    // softmax per row (one warp per row group)
    {
        int wrp = tid >> 5, lane = tid & 31;
        for (int b = wrp; b < BATCH; b += 8) {
            float v0 = wsm[b * 64 + lane];
            float v1 = wsm[b * 64 + 32 + lane];
            float m = fmaxf(v0, v1);
            #pragma unroll
            for (int o = 16; o; o >>= 1) m = fmaxf(m, __shfl_xor_sync(0xffffffffu, m, o));
            float e0 = __expf(v0 - m), e1 = __expf(v1 - m);
            float s = e0 + e1;
            #pragma unroll
            for (int o = 16; o; o >>= 1) s += __shfl_xor_sync(0xffffffffu, s, o);
            wsm[b * 64 + lane]      = e0 / s;
            wsm[b * 64 + 32 + lane] = e1 / s;
        }
    }
    __syncthreads();

    // write w to out, and compute per-channel entropy contributions
    for (int i = tid; i < NCHAN; i += 256) {
        float wv = wsm[i];
        out[BATCH * NC + i] = wv;   // offset 160
        float S0v = g_red[1 * NCHAN + i], T0v = g_red[2 * NCHAN + i];
        float S1v = g_red[3 * NCHAN + i], T1v = g_red[4 * NCHAN + i];
        float lw = __logf(wv);
        float s0 = wv * S0v + 1e-12f;
        float e0 = (wv * S0v / s0) * (__logf(s0) - lw) - wv * T0v / s0;
        float s1 = wv * S1v + 1e-12f;
        float e1 = (wv * S1v / s1) * (__logf(s1) - lw) - wv * T1v / s1;
        c0s[i] = e0 * wv;
        c1s[i] = e1 * wv;
    }
    __syncthreads();

    // f[b,k] = sum_c feats*w / (sum_c w + 1e-6)
    if (tid < BATCH * 2) {
        int b = tid >> 1, k = tid & 1;
        const float* cs = (k == 0) ? c0s : c1s;
        float acc = 0.f, ws = 0.f;
        #pragma unroll 8
        for (int c = 0; c < CH; ++c) {
            acc += cs[b * CH + c];
            ws  += wsm[b * CH + c];
        }
        float fv = acc / (ws + 1e-6f);
        fbuf[b * 2 + k] = fv;
        out[BATCH * NC + NCHAN + b * 2 + k] = fv;   // offset 2208
    }
    __syncthreads();

    // m = relu(f @ cls1_w^T + cls1_b)   [32,128]  (reuse c1s)
    float* mbuf = c1s;
    for (int i = tid; i < BATCH * MLPD; i += 256) {
        int b = i >> 7, j = i & 127;
        float mv = fbuf[b * 2] * cls1_w[j * 2] + fbuf[b * 2 + 1] * cls1_w[j * 2 + 1] + cls1_b[j];
        mbuf[i] = fmaxf(mv, 0.f);
    }
    __syncthreads();

    // logits = m @ cls2_w^T + cls2_b   [32,5]
    for (int i = tid; i < BATCH * NC; i += 256) {
        int b = i / NC, n = i % NC;
        float acc = cls2_b[n];
        const float* wr = cls2_w + n * MLPD;
        const float* mr = mbuf + b * MLPD;
        #pragma unroll 8
        for (int j = 0; j < MLPD; ++j) acc += mr[j] * wr[j];
        out[i] = acc;
    }
}

extern "C" void kernel_launch(void* const* d_in, const int* in_sizes, int n_in,
                              void* d_out, int out_size) {
    const float* x      = (const float*)d_in[0];
    const float* fc1_w  = (const float*)d_in[1];
    const float* fc1_b  = (const float*)d_in[2];
    const float* fc2_w  = (const float*)d_in[3];
    const float* fc2_b  = (const float*)d_in[4];
    const float* cls1_w = (const float*)d_in[5];
    const float* cls1_b = (const float*)d_in[6];
    const float* cls2_w = (const float*)d_in[7];
    const float* cls2_b = (const float*)d_in[8];
    float* out = (float*)d_out;

    topo_reduce_kernel<<<NCHAN, 64>>>(x);
    head_kernel<<<1, 256>>>(fc1_w, fc1_b, fc2_w, fc2_b,
                            cls1_w, cls1_b, cls2_w, cls2_b, out);
}

// round 2
// speedup vs baseline: 2.0126x; 2.0126x over previous
#include <cuda_runtime.h>
#include <math.h>

#define BATCH 32
#define CH    64
#define HH    256
#define WW    256
#define NCHAN 2048

__device__ float g_red[5 * NCHAN];   // [0]=sum(x) [1]=S0 [2]=T0 [3]=S1 [4]=T1
__device__ unsigned int g_cnt = 0;

// ---- shared memory layout (floats) ----
#define OFF_FC1W 0        // 2048   (reused as c0s)
#define OFF_FC2W 2048     // 2048   (reused as c1s)
#define OFF_Z    4096     // 2048 transposed z[c][b]  (reused as mbuf[4096])
#define OFF_H    6144     // 1024 transposed h[j][b]
#define OFF_WSM  7168     // 2048 w[b][c]
#define OFF_C1W  9216     // 256
#define OFF_C2W  9472     // 640
#define OFF_F1B  10112    // 32
#define OFF_F2B  10144    // 64
#define OFF_C1B  10208    // 128
#define OFF_C2B  10336    // 5 (pad to 8)
#define OFF_FBUF 10344    // 64
#define SMEM_FLOATS 10416

// One topo step: input row `ir` lives in vb[P]; writes row ir's horizontal
// max/min into slot P; finalizes output row ir-1 (rows ir-2..ir = all 3 slots).
template<int P>
__device__ __forceinline__ void topo_step(
    const float* __restrict__ base, int ir, int ir_end, int r0, int lane,
    float (&vb)[3][8], float (&hx)[3][8], float (&hn)[3][8],
    float& zacc, float& S0, float& T0, float& S1, float& T1)
{
    constexpr int PN = (P + 1) % 3;
    constexpr int PM = (P + 2) % 3;
    // prefetch next row into slot PN
    if (ir < ir_end) {
        const float* p = base + (ir + 1) * WW + lane * 8;
        float4 a = *(const float4*)p;
        float4 b = *(const float4*)(p + 4);
        vb[PN][0]=a.x; vb[PN][1]=a.y; vb[PN][2]=a.z; vb[PN][3]=a.w;
        vb[PN][4]=b.x; vb[PN][5]=b.y; vb[PN][6]=b.z; vb[PN][7]=b.w;
    }
    float* v = vb[P];
    if (ir >= r0 && ir < r0 + 32)
        zacc += ((v[0]+v[1])+(v[2]+v[3])) + ((v[4]+v[5])+(v[6]+v[7]));

    float L = __shfl_up_sync(0xffffffffu, v[7], 1);
    float R = __shfl_down_sync(0xffffffffu, v[0], 1);
    float Lx = (lane > 0)  ? L : -INFINITY;
    float Ln = (lane > 0)  ? L :  INFINITY;
    float Rx = (lane < 31) ? R : -INFINITY;
    float Rn = (lane < 31) ? R :  INFINITY;

    float px[7], pn[7];
    #pragma unroll
    for (int i = 0; i < 7; ++i) { px[i] = fmaxf(v[i], v[i+1]); pn[i] = fminf(v[i], v[i+1]); }
    hx[P][0] = fmaxf(Lx, px[0]);  hn[P][0] = fminf(Ln, pn[0]);
    #pragma unroll
    for (int i = 1; i < 7; ++i) { hx[P][i] = fmaxf(px[i-1], v[i+1]); hn[P][i] = fminf(pn[i-1], v[i+1]); }
    hx[P][7] = fmaxf(px[6], Rx);  hn[P][7] = fminf(pn[6], Rn);

    if (ir - 1 >= r0) {   // finalize output row ir-1 (yp = row ir-1 in slot PM)
        float* yp = vb[PM];
        #pragma unroll
        for (int i = 0; i < 8; ++i) {
            float mx  = fmaxf(hx[0][i], fmaxf(hx[1][i], hx[2][i]));
            float mn2 = fminf(hn[0][i], fminf(hn[1][i], hn[2][i]));
            float l0 = mx - yp[i];
            float l1 = yp[i] - mn2;
            S0 += l0; S1 += l1;
            T0 += l0 * __logf(fmaxf(l0, 1e-35f));
            T1 += l1 * __logf(fmaxf(l1, 1e-35f));
        }
    }
}

__global__ __launch_bounds__(256, 2)
void topo_fused_kernel(const float* __restrict__ x,
                       const float* __restrict__ fc1_w, const float* __restrict__ fc1_b,
                       const float* __restrict__ fc2_w, const float* __restrict__ fc2_b,
                       const float* __restrict__ cls1_w, const float* __restrict__ cls1_b,
                       const float* __restrict__ cls2_w, const float* __restrict__ cls2_b,
                       float* __restrict__ out)
{
    __shared__ __align__(16) float S[SMEM_FLOATS];
    __shared__ int s_last;

    const int ch   = blockIdx.x;
    const int tid  = threadIdx.x;
    const int wrp  = tid >> 5;
    const int lane = tid & 31;
    const float* __restrict__ base = x + (size_t)ch * (HH * WW);

    const int r0       = wrp * 32;
    const int ir_begin = (r0 == 0) ? 0 : (r0 - 1);
    const int ir_end   = (r0 + 32 > 255) ? 255 : (r0 + 32);

    float vb[3][8], hx[3][8], hn[3][8];
    #pragma unroll
    for (int s = 0; s < 3; ++s)
        #pragma unroll
        for (int i = 0; i < 8; ++i) { hx[s][i] = -INFINITY; hn[s][i] = INFINITY; }

    // load first row into slot 0
    {
        const float* p = base + ir_begin * WW + lane * 8;
        float4 a = *(const float4*)p;
        float4 b = *(const float4*)(p + 4);
        vb[0][0]=a.x; vb[0][1]=a.y; vb[0][2]=a.z; vb[0][3]=a.w;
        vb[0][4]=b.x; vb[0][5]=b.y; vb[0][6]=b.z; vb[0][7]=b.w;
    }

    float zacc=0.f, S0=0.f, T0=0.f, S1=0.f, T1=0.f;

    int ir = ir_begin;
    while (ir + 2 <= ir_end) {
        topo_step<0>(base, ir,   ir_end, r0, lane, vb, hx, hn, zacc, S0, T0, S1, T1);
        topo_step<1>(base, ir+1, ir_end, r0, lane, vb, hx, hn, zacc, S0, T0, S1, T1);
        topo_step<2>(base, ir+2, ir_end, r0, lane, vb, hx, hn, zacc, S0, T0, S1, T1);
        ir += 3;
    }
    if (ir <= ir_end)   // trip counts are 33 or 34 -> remainder step has phase 0
        topo_step<0>(base, ir, ir_end, r0, lane, vb, hx, hn, zacc, S0, T0, S1, T1);

    if (r0 + 32 > 255) {
        // wrp 7 tail: output row 255, window rows 254 (slot1), 255 (slot2); y = slot2
        #pragma unroll
        for (int i = 0; i < 8; ++i) {
            float mx  = fmaxf(hx[1][i], hx[2][i]);
            float mn2 = fminf(hn[1][i], hn[2][i]);
            float l0 = mx - vb[2][i];
            float l1 = vb[2][i] - mn2;
            S0 += l0; S1 += l1;
            T0 += l0 * __logf(fmaxf(l0, 1e-35f));
            T1 += l1 * __logf(fmaxf(l1, 1e-35f));
        }
    }

    // warp reduce 5 accumulators
    #pragma unroll
    for (int o = 16; o; o >>= 1) {
        zacc += __shfl_down_sync(0xffffffffu, zacc, o);
        S0   += __shfl_down_sync(0xffffffffu, S0,   o);
        T0   += __shfl_down_sync(0xffffffffu, T0,   o);
        S1   += __shfl_down_sync(0xffffffffu, S1,   o);
        T1   += __shfl_down_sync(0xffffffffu, T1,   o);
    }
    if (lane == 0) {
        S[0*8 + wrp] = zacc; S[1*8 + wrp] = S0; S[2*8 + wrp] = T0;
        S[3*8 + wrp] = S1;   S[4*8 + wrp] = T1;
    }
    __syncthreads();
    if (tid < 5) {
        float a = 0.f;
        #pragma unroll
        for (int j = 0; j < 8; ++j) a += S[tid*8 + j];
        g_red[tid * NCHAN + ch] = a;
    }
    __threadfence();
    __syncthreads();
    if (tid == 0) s_last = (atomicAdd(&g_cnt, 1u) == (unsigned)(gridDim.x - 1));
    __syncthreads();
    if (!s_last) return;

    // ======================= HEAD (last block only) =======================
    __threadfence();

    // stage weights (coalesced float4)
    for (int i = tid; i < 512; i += 256) ((float4*)(S+OFF_FC1W))[i] = ((const float4*)fc1_w)[i];
    for (int i = tid; i < 512; i += 256) ((float4*)(S+OFF_FC2W))[i] = ((const float4*)fc2_w)[i];
    for (int i = tid; i < 64;  i += 256) ((float4*)(S+OFF_C1W))[i]  = ((const float4*)cls1_w)[i];
    for (int i = tid; i < 160; i += 256) ((float4*)(S+OFF_C2W))[i]  = ((const float4*)cls2_w)[i];
    if (tid < 32)  S[OFF_F1B + tid] = fc1_b[tid];
    if (tid < 64)  S[OFF_F2B + tid] = fc2_b[tid];
    if (tid < 128) S[OFF_C1B + tid] = cls1_b[tid];
    if (tid < 5)   S[OFF_C2B + tid] = cls2_b[tid];
    // z transposed: z_T[c*32+b]
    for (int i = tid; i < NCHAN; i += 256) {
        int c = i >> 5, b = i & 31;
        S[OFF_Z + i] = __ldcg(&g_red[b * CH + c]) * (1.f / 65536.f);
    }
    __syncthreads();

    // h_T[j][b] = relu(z @ fc1_w^T + b)
    for (int i = tid; i < BATCH * 32; i += 256) {
        int j = i >> 5, b = i & 31;
        float acc = S[OFF_F1B + j];
        const float* wr = S + OFF_FC1W + j * CH;
        #pragma unroll
        for (int c = 0; c < CH; ++c) acc += S[OFF_Z + c*32 + b] * wr[c];
        S[OFF_H + j*32 + b] = fmaxf(acc, 0.f);
    }
    __syncthreads();

    // wsm[b][c] = pre-softmax logits
    for (int i = tid; i < NCHAN; i += 256) {
        int c = i >> 5, b = i & 31;
        float acc = S[OFF_F2B + c];
        const float* wr = S + OFF_FC2W + c * 32;
        #pragma unroll
        for (int j = 0; j < 32; ++j) acc += S[OFF_H + j*32 + b] * wr[j];
        S[OFF_WSM + b*CH + c] = acc;
    }
    __syncthreads();

    // softmax per batch row (warp per row)
    for (int b = wrp; b < BATCH; b += 8) {
        float v0 = S[OFF_WSM + b*CH + lane];
        float v1 = S[OFF_WSM + b*CH + 32 + lane];
        float m = fmaxf(v0, v1);
        #pragma unroll
        for (int o = 16; o; o >>= 1) m = fmaxf(m, __shfl_xor_sync(0xffffffffu, m, o));
        float e0 = __expf(v0 - m), e1 = __expf(v1 - m);
        float s = e0 + e1;
        #pragma unroll
        for (int o = 16; o; o >>= 1) s += __shfl_xor_sync(0xffffffffu, s, o);
        float inv = 1.f / s;
        S[OFF_WSM + b*CH + lane]      = e0 * inv;
        S[OFF_WSM + b*CH + 32 + lane] = e1 * inv;
    }
    __syncthreads();

    // per-channel entropy (closed form), write w to out
    for (int i = tid; i < NCHAN; i += 256) {
        float wv = S[OFF_WSM + i];
        out[BATCH*5 + i] = wv;
        float s0v = __ldcg(&g_red[1*NCHAN + i]);
        float t0v = __ldcg(&g_red[2*NCHAN + i]);
        float s1v = __ldcg(&g_red[3*NCHAN + i]);
        float t1v = __ldcg(&g_red[4*NCHAN + i]);
        float lw = __logf(wv);
        float a0 = wv * s0v, s0 = a0 + 1e-12f;
        float e0 = (a0 / s0) * (__logf(s0) - lw) - wv * t0v / s0;
        float a1 = wv * s1v, s1 = a1 + 1e-12f;
        float e1 = (a1 / s1) * (__logf(s1) - lw) - wv * t1v / s1;
        S[OFF_FC1W + i] = e0 * wv;   // c0s
        S[OFF_FC2W + i] = e1 * wv;   // c1s
    }
    __syncthreads();

    // f[b][k]
    if (tid < BATCH * 2) {
        int b = tid >> 1, k = tid & 1;
        const float* cs = S + (k == 0 ? OFF_FC1W : OFF_FC2W) + b*CH;
        float acc = 0.f, ws = 0.f;
        #pragma unroll
        for (int c = 0; c < CH; ++c) { acc += cs[c]; ws += S[OFF_WSM + b*CH + c]; }
        float fv = acc / (ws + 1e-6f);
        S[OFF_FBUF + tid] = fv;
        out[BATCH*5 + NCHAN + tid] = fv;
    }
    __syncthreads();

    // m[b][j] = relu(f @ cls1_w^T + b)  -> reuse OFF_Z (z/h/wsm dead)
    for (int i = tid; i < BATCH * 128; i += 256) {
        int b = i >> 7, j = i & 127;
        float mv = S[OFF_FBUF + 2*b] * S[OFF_C1W + 2*j]
                 + S[OFF_FBUF + 2*b + 1] * S[OFF_C1W + 2*j + 1]
                 + S[OFF_C1B + j];
        S[OFF_Z + i] = fmaxf(mv, 0.f);
    }
    __syncthreads();

    // logits
    for (int i = tid; i < BATCH * 5; i += 256) {
        int b = i / 5, n = i - b * 5;
        float acc = S[OFF_C2B + n];
        const float* wr = S + OFF_C2W + n * 128;
        const float* mr = S + OFF_Z + b * 128;
        #pragma unroll
        for (int j = 0; j < 128; ++j) acc += mr[j] * wr[j];
        out[i] = acc;
    }
    if (tid == 0) g_cnt = 0;   // reset for next graph replay
}

extern "C" void kernel_launch(void* const* d_in, const int* in_sizes, int n_in,
                              void* d_out, int out_size) {
    const float* x      = (const float*)d_in[0];
    const float* fc1_w  = (const float*)d_in[1];
    const float* fc1_b  = (const float*)d_in[2];
    const float* fc2_w  = (const float*)d_in[3];
    const float* fc2_b  = (const float*)d_in[4];
    const float* cls1_w = (const float*)d_in[5];
    const float* cls1_b = (const float*)d_in[6];
    const float* cls2_w = (const float*)d_in[7];
    const float* cls2_b = (const float*)d_in[8];
    float* out = (float*)d_out;

    topo_fused_kernel<<<NCHAN, 256>>>(x, fc1_w, fc1_b, fc2_w, fc2_b,
                                      cls1_w, cls1_b, cls2_w, cls2_b, out);
}

// round 3
// speedup vs baseline: 2.2546x; 1.1203x over previous
#include <cuda_runtime.h>
#include <math.h>

#define BATCH 32
#define CH    64
#define HH    256
#define WW    256
#define NCHAN 2048

__device__ float g_red[5 * NCHAN];   // [0]=sum(x) [1]=S0 [2]=T0 [3]=S1 [4]=T1
__device__ unsigned int g_cnt = 0;

// ---- shared memory layout (floats) ----
#define OFF_FC1W 0        // 2048   (reused as c0s)
#define OFF_FC2W 2048     // 2048   (reused as c1s)
#define OFF_Z    4096     // 2048 transposed z[c][b]  (reused as mbuf)
#define OFF_H    6144     // 1024 transposed h[j][b]
#define OFF_WSM  7168     // 2048 w[b][c]
#define OFF_C1W  9216     // 256
#define OFF_C2W  9472     // 640
#define OFF_F1B  10112    // 32
#define OFF_F2B  10144    // 64
#define OFF_C1B  10208    // 128
#define OFF_C2B  10336    // 8
#define OFF_FBUF 10344    // 64
#define SMEM_FLOATS 10416

// Load one row (8 elts/lane) and compute horizontal 3-window max/min.
__device__ __forceinline__ void load_h(const float* __restrict__ p, bool eL, bool eR,
                                       float* __restrict__ v,
                                       float* __restrict__ hx, float* __restrict__ hn)
{
    float4 a = *(const float4*)p;
    float4 b = *(const float4*)(p + 4);
    v[0]=a.x; v[1]=a.y; v[2]=a.z; v[3]=a.w;
    v[4]=b.x; v[5]=b.y; v[6]=b.z; v[7]=b.w;

    float L = __shfl_up_sync(0xffffffffu, v[7], 1);
    float R = __shfl_down_sync(0xffffffffu, v[0], 1);
    float Lx = eL ? -INFINITY : L;
    float Ln = eL ?  INFINITY : L;
    float Rx = eR ? -INFINITY : R;
    float Rn = eR ?  INFINITY : R;

    float px[7], pn[7];
    #pragma unroll
    for (int i = 0; i < 7; ++i) { px[i] = fmaxf(v[i], v[i+1]); pn[i] = fminf(v[i], v[i+1]); }
    hx[0] = fmaxf(Lx, px[0]);  hn[0] = fminf(Ln, pn[0]);
    #pragma unroll
    for (int i = 1; i < 7; ++i) { hx[i] = fmaxf(px[i-1], v[i+1]); hn[i] = fminf(pn[i-1], v[i+1]); }
    hx[7] = fmaxf(px[6], Rx);  hn[7] = fminf(pn[6], Rn);
}

// One steady-state step (phase P): loads input row (out_row+1) into slot P,
// finalizes output row out_row (y = vs[Q]), updates q.
template<int P>
__device__ __forceinline__ void topo_step(
    const float* __restrict__ p, bool eL, bool eR,
    float (&vs)[2][8], float (&hxs)[2][8], float (&hns)[2][8],
    float (&qx)[8], float (&qn)[8],
    float& zacc, float& S0, float& T0, float& S1, float& T1)
{
    constexpr int Q = P ^ 1;
    load_h(p, eL, eR, vs[P], hxs[P], hns[P]);
    #pragma unroll
    for (int i = 0; i < 8; ++i) {
        float mx = fmaxf(qx[i], hxs[P][i]);
        float mn = fminf(qn[i], hns[P][i]);
        float y  = vs[Q][i];
        float l0 = mx - y;
        float l1 = y - mn;
        zacc += y;
        S0 += l0; S1 += l1;
        T0 += l0 * __log2f(fmaxf(l0, 1e-35f));
        T1 += l1 * __log2f(fmaxf(l1, 1e-35f));
        qx[i] = fmaxf(hxs[Q][i], hxs[P][i]);
        qn[i] = fminf(hns[Q][i], hns[P][i]);
    }
}

__global__ __launch_bounds__(256, 3)
void topo_fused_kernel(const float* __restrict__ x,
                       const float* __restrict__ fc1_w, const float* __restrict__ fc1_b,
                       const float* __restrict__ fc2_w, const float* __restrict__ fc2_b,
                       const float* __restrict__ cls1_w, const float* __restrict__ cls1_b,
                       const float* __restrict__ cls2_w, const float* __restrict__ cls2_b,
                       float* __restrict__ out)
{
    __shared__ __align__(16) float S[SMEM_FLOATS];
    __shared__ int s_last;

    const int ch   = blockIdx.x;
    const int tid  = threadIdx.x;
    const int wrp  = tid >> 5;
    const int lane = tid & 31;
    const bool eL = (lane == 0), eR = (lane == 31);
    const float* __restrict__ base = x + (size_t)ch * (HH * WW) + lane * 8;

    const int r0 = wrp * 32;          // output rows r0 .. r0+31
    const int ra = (r0 == 0) ? 0 : (r0 - 1);

    float vs[2][8], hxs[2][8], hns[2][8], qx[8], qn[8];
    float zacc = 0.f, S0 = 0.f, T0 = 0.f, S1 = 0.f, T1 = 0.f;

    // prologue: slot1 <- row r0-1 (or row 0 dup), slot0 <- row r0
    load_h(base + ra * WW, eL, eR, vs[1], hxs[1], hns[1]);
    load_h(base + r0 * WW, eL, eR, vs[0], hxs[0], hns[0]);
    #pragma unroll
    for (int i = 0; i < 8; ++i) {
        qx[i] = fmaxf(hxs[1][i], hxs[0][i]);
        qn[i] = fminf(hns[1][i], hns[0][i]);
    }

    // iterations k = 0..31: out row r0+k, load row r0+k+1 (clamped for warp 7)
    const float* p = base + (r0 + 1) * WW;
    #pragma unroll 1
    for (int k = 0; k < 30; k += 2) {
        topo_step<1>(p, eL, eR, vs, hxs, hns, qx, qn, zacc, S0, T0, S1, T1); p += WW;
        topo_step<0>(p, eL, eR, vs, hxs, hns, qx, qn, zacc, S0, T0, S1, T1); p += WW;
    }
    topo_step<1>(p, eL, eR, vs, hxs, hns, qx, qn, zacc, S0, T0, S1, T1);   // row r0+31
    const float* pl = (r0 + 32 > 255) ? p : (p + WW);                      // warp7: reload 255 (L1)
    topo_step<0>(pl, eL, eR, vs, hxs, hns, qx, qn, zacc, S0, T0, S1, T1);  // row r0+32 / clamp

    // warp reduce
    #pragma unroll
    for (int o = 16; o; o >>= 1) {
        zacc += __shfl_down_sync(0xffffffffu, zacc, o);
        S0   += __shfl_down_sync(0xffffffffu, S0,   o);
        T0   += __shfl_down_sync(0xffffffffu, T0,   o);
        S1   += __shfl_down_sync(0xffffffffu, S1,   o);
        T1   += __shfl_down_sync(0xffffffffu, T1,   o);
    }
    if (lane == 0) {
        S[0*8 + wrp] = zacc;
        S[1*8 + wrp] = S0;
        S[2*8 + wrp] = T0 * 0.69314718056f;   // log2 -> ln
        S[3*8 + wrp] = S1;
        S[4*8 + wrp] = T1 * 0.69314718056f;
    }
    __syncthreads();
    if (tid < 5) {
        float a = 0.f;
        #pragma unroll
        for (int j = 0; j < 8; ++j) a += S[tid*8 + j];
        g_red[tid * NCHAN + ch] = a;
    }
    __threadfence();
    __syncthreads();
    if (tid == 0) s_last = (atomicAdd(&g_cnt, 1u) == (unsigned)(gridDim.x - 1));
    __syncthreads();
    if (!s_last) return;

    // ======================= HEAD (last block only) =======================
    __threadfence();

    for (int i = tid; i < 512; i += 256) ((float4*)(S+OFF_FC1W))[i] = ((const float4*)fc1_w)[i];
    for (int i = tid; i < 512; i += 256) ((float4*)(S+OFF_FC2W))[i] = ((const float4*)fc2_w)[i];
    for (int i = tid; i < 64;  i += 256) ((float4*)(S+OFF_C1W))[i]  = ((const float4*)cls1_w)[i];
    for (int i = tid; i < 160; i += 256) ((float4*)(S+OFF_C2W))[i]  = ((const float4*)cls2_w)[i];
    if (tid < 32)  S[OFF_F1B + tid] = fc1_b[tid];
    if (tid < 64)  S[OFF_F2B + tid] = fc2_b[tid];
    if (tid < 128) S[OFF_C1B + tid] = cls1_b[tid];
    if (tid < 5)   S[OFF_C2B + tid] = cls2_b[tid];
    for (int i = tid; i < NCHAN; i += 256) {       // z transposed z_T[c][b]
        int c = i >> 5, b = i & 31;
        S[OFF_Z + i] = __ldcg(&g_red[b * CH + c]) * (1.f / 65536.f);
    }
    __syncthreads();

    // h_T[j][b] = relu(z @ fc1_w^T + b)
    for (int i = tid; i < BATCH * 32; i += 256) {
        int j = i >> 5, b = i & 31;
        float acc = S[OFF_F1B + j];
        const float* wr = S + OFF_FC1W + j * CH;
        #pragma unroll
        for (int c = 0; c < CH; ++c) acc += S[OFF_Z + c*32 + b] * wr[c];
        S[OFF_H + j*32 + b] = fmaxf(acc, 0.f);
    }
    __syncthreads();

    // pre-softmax logits
    for (int i = tid; i < NCHAN; i += 256) {
        int c = i >> 5, b = i & 31;
        float acc = S[OFF_F2B + c];
        const float* wr = S + OFF_FC2W + c * 32;
        #pragma unroll
        for (int j = 0; j < 32; ++j) acc += S[OFF_H + j*32 + b] * wr[j];
        S[OFF_WSM + b*CH + c] = acc;
    }
    __syncthreads();

    // softmax per row
    for (int b = wrp; b < BATCH; b += 8) {
        float v0 = S[OFF_WSM + b*CH + lane];
        float v1 = S[OFF_WSM + b*CH + 32 + lane];
        float m = fmaxf(v0, v1);
        #pragma unroll
        for (int o = 16; o; o >>= 1) m = fmaxf(m, __shfl_xor_sync(0xffffffffu, m, o));
        float e0 = __expf(v0 - m), e1 = __expf(v1 - m);
        float s = e0 + e1;
        #pragma unroll
        for (int o = 16; o; o >>= 1) s += __shfl_xor_sync(0xffffffffu, s, o);
        float inv = 1.f / s;
        S[OFF_WSM + b*CH + lane]      = e0 * inv;
        S[OFF_WSM + b*CH + 32 + lane] = e1 * inv;
    }
    __syncthreads();

    // entropy closed form, write w
    for (int i = tid; i < NCHAN; i += 256) {
        float wv = S[OFF_WSM + i];
        out[BATCH*5 + i] = wv;
        float s0v = __ldcg(&g_red[1*NCHAN + i]);
        float t0v = __ldcg(&g_red[2*NCHAN + i]);
        float s1v = __ldcg(&g_red[3*NCHAN + i]);
        float t1v = __ldcg(&g_red[4*NCHAN + i]);
        float lw = __logf(wv);
        float a0 = wv * s0v, s0 = a0 + 1e-12f;
        float e0 = (a0 / s0) * (__logf(s0) - lw) - wv * t0v / s0;
        float a1 = wv * s1v, s1 = a1 + 1e-12f;
        float e1 = (a1 / s1) * (__logf(s1) - lw) - wv * t1v / s1;
        S[OFF_FC1W + i] = e0 * wv;
        S[OFF_FC2W + i] = e1 * wv;
    }
    __syncthreads();

    if (tid < BATCH * 2) {
        int b = tid >> 1, k = tid & 1;
        const float* cs = S + (k == 0 ? OFF_FC1W : OFF_FC2W) + b*CH;
        float acc = 0.f, ws = 0.f;
        #pragma unroll
        for (int c = 0; c < CH; ++c) { acc += cs[c]; ws += S[OFF_WSM + b*CH + c]; }
        float fv = acc / (ws + 1e-6f);
        S[OFF_FBUF + tid] = fv;
        out[BATCH*5 + NCHAN + tid] = fv;
    }
    __syncthreads();

    for (int i = tid; i < BATCH * 128; i += 256) {
        int b = i >> 7, j = i & 127;
        float mv = S[OFF_FBUF + 2*b] * S[OFF_C1W + 2*j]
                 + S[OFF_FBUF + 2*b + 1] * S[OFF_C1W + 2*j + 1]
                 + S[OFF_C1B + j];
        S[OFF_Z + i] = fmaxf(mv, 0.f);
    }
    __syncthreads();

    for (int i = tid; i < BATCH * 5; i += 256) {
        int b = i / 5, n = i - b * 5;
        float acc = S[OFF_C2B + n];
        const float* wr = S + OFF_C2W + n * 128;
        const float* mr = S + OFF_Z + b * 128;
        #pragma unroll
        for (int j = 0; j < 128; ++j) acc += mr[j] * wr[j];
        out[i] = acc;
    }
    if (tid == 0) g_cnt = 0;
}

extern "C" void kernel_launch(void* const* d_in, const int* in_sizes, int n_in,
                              void* d_out, int out_size) {
    const float* x      = (const float*)d_in[0];
    const float* fc1_w  = (const float*)d_in[1];
    const float* fc1_b  = (const float*)d_in[2];
    const float* fc2_w  = (const float*)d_in[3];
    const float* fc2_b  = (const float*)d_in[4];
    const float* cls1_w = (const float*)d_in[5];
    const float* cls1_b = (const float*)d_in[6];
    const float* cls2_w = (const float*)d_in[7];
    const float* cls2_b = (const float*)d_in[8];
    float* out = (float*)d_out;

    topo_fused_kernel<<<NCHAN, 256>>>(x, fc1_w, fc1_b, fc2_w, fc2_b,
                                      cls1_w, cls1_b, cls2_w, cls2_b, out);
}

// round 4
// speedup vs baseline: 2.3587x; 1.0462x over previous
#include <cuda_runtime.h>
#include <math.h>

#define BATCH 32
#define CH    64
#define HH    256
#define WW    256
#define NCHAN 2048

__device__ float g_red[5 * NCHAN];   // [0]=sum(x) [1]=S0 [2]=T0 [3]=S1 [4]=T1
__device__ unsigned int g_cnt = 0;

// ---- shared memory layout (floats) ----
#define OFF_FC1W 0
#define OFF_FC2W 2048
#define OFF_Z    4096
#define OFF_H    6144
#define OFF_WSM  7168
#define OFF_C1W  9216
#define OFF_C2W  9472
#define OFF_F1B  10112
#define OFF_F2B  10144
#define OFF_C1B  10208
#define OFF_C2B  10336
#define OFF_FBUF 10344
#define SMEM_FLOATS 10416

__device__ __forceinline__ void load8(const float* __restrict__ p, float* __restrict__ v) {
    float4 a = *(const float4*)p;
    float4 b = *(const float4*)(p + 4);
    v[0]=a.x; v[1]=a.y; v[2]=a.z; v[3]=a.w;
    v[4]=b.x; v[5]=b.y; v[6]=b.z; v[7]=b.w;
}

// One step, phase P: cur = v[P] (row r), next = v[P^1] (row r+1).
// prx/prn hold max/min over rows (r-1, r). Prefetches row r+2 into v[P].
template<int P>
__device__ __forceinline__ void topo_step(
    const float* __restrict__ pf, bool eL, bool eR,
    float (&v)[2][8], float (&prx)[8], float (&prn)[8],
    float& zacc, float& S0, float& T0, float& S1, float& T1)
{
    constexpr int Q = P ^ 1;
    float vf[8];
    load8(pf, vf);

    const float* cur = v[P];
    const float* nx  = v[Q];

    // vertical 3-row max/min for edge columns (needed before shuffles)
    float vx7 = fmaxf(prx[7], nx[7]);
    float vn7 = fminf(prn[7], nx[7]);
    float vx0 = fmaxf(prx[0], nx[0]);
    float vn0 = fminf(prn[0], nx[0]);

    float Lxr = __shfl_up_sync(0xffffffffu, vx7, 1);
    float Lnr = __shfl_up_sync(0xffffffffu, vn7, 1);
    float Rxr = __shfl_down_sync(0xffffffffu, vx0, 1);
    float Rnr = __shfl_down_sync(0xffffffffu, vn0, 1);
    float ax = eL ? -INFINITY : Lxr;     // vx[-1]
    float an = eL ?  INFINITY : Lnr;
    float Rx = eR ? -INFINITY : Rxr;     // vx[8]
    float Rn = eR ?  INFINITY : Rnr;

    // rolling horizontal 3-tap over just-in-time vertical results
    float bx = vx0, bn = vn0;
    #pragma unroll
    for (int i = 0; i < 8; ++i) {
        float cx = (i < 7) ? fmaxf(prx[i+1], nx[i+1]) : Rx;
        float cn = (i < 7) ? fminf(prn[i+1], nx[i+1]) : Rn;
        float mx = fmaxf(ax, fmaxf(bx, cx));
        float mn = fminf(an, fminf(bn, cn));
        float y  = cur[i];
        zacc += y;
        float l0 = mx - y;
        float l1 = y - mn;
        S0 += l0; S1 += l1;
        T0 += l0 * __log2f(l0 + 1e-35f);
        T1 += l1 * __log2f(l1 + 1e-35f);
        ax = bx; bx = cx;
        an = bn; bn = cn;
    }
    // pair over (r, r+1) for next iteration; cur slot becomes future row
    #pragma unroll
    for (int i = 0; i < 8; ++i) {
        prx[i] = fmaxf(cur[i], nx[i]);
        prn[i] = fminf(cur[i], nx[i]);
    }
    #pragma unroll
    for (int i = 0; i < 8; ++i) v[P][i] = vf[i];
}

__global__ __launch_bounds__(256, 4)
void topo_fused_kernel(const float* __restrict__ x,
                       const float* __restrict__ fc1_w, const float* __restrict__ fc1_b,
                       const float* __restrict__ fc2_w, const float* __restrict__ fc2_b,
                       const float* __restrict__ cls1_w, const float* __restrict__ cls1_b,
                       const float* __restrict__ cls2_w, const float* __restrict__ cls2_b,
                       float* __restrict__ out)
{
    __shared__ __align__(16) float S[SMEM_FLOATS];
    __shared__ int s_last;

    const int ch   = blockIdx.x;
    const int tid  = threadIdx.x;
    const int wrp  = tid >> 5;
    const int lane = tid & 31;
    const bool eL = (lane == 0), eR = (lane == 31);
    const float* __restrict__ base = x + (size_t)ch * (HH * WW) + lane * 8;

    const int r0 = wrp * 32;                   // output rows r0 .. r0+31
    const int ra = (r0 == 0) ? 0 : (r0 - 1);

    float v[2][8], prx[8], prn[8];
    float zacc = 0.f, S0 = 0.f, T0 = 0.f, S1 = 0.f, T1 = 0.f;

    {
        float vp[8];
        load8(base + ra * WW, vp);             // row r0-1 (clamped)
        load8(base + r0 * WW, v[0]);           // cur  = row r0
        load8(base + (r0 + 1) * WW, v[1]);     // next = row r0+1
        #pragma unroll
        for (int i = 0; i < 8; ++i) {
            prx[i] = fmaxf(vp[i], v[0][i]);
            prn[i] = fminf(vp[i], v[0][i]);
        }
    }

    #pragma unroll 1
    for (int k = 0; k < 32; k += 2) {
        int r2 = r0 + k + 2; if (r2 > 255) r2 = 255;
        topo_step<0>(base + r2 * WW, eL, eR, v, prx, prn, zacc, S0, T0, S1, T1);
        int r3 = r0 + k + 3; if (r3 > 255) r3 = 255;
        topo_step<1>(base + r3 * WW, eL, eR, v, prx, prn, zacc, S0, T0, S1, T1);
    }

    // warp reduce 5 accumulators
    #pragma unroll
    for (int o = 16; o; o >>= 1) {
        zacc += __shfl_down_sync(0xffffffffu, zacc, o);
        S0   += __shfl_down_sync(0xffffffffu, S0,   o);
        T0   += __shfl_down_sync(0xffffffffu, T0,   o);
        S1   += __shfl_down_sync(0xffffffffu, S1,   o);
        T1   += __shfl_down_sync(0xffffffffu, T1,   o);
    }
    if (lane == 0) {
        S[0*8 + wrp] = zacc;
        S[1*8 + wrp] = S0;
        S[2*8 + wrp] = T0 * 0.69314718056f;    // log2 -> ln
        S[3*8 + wrp] = S1;
        S[4*8 + wrp] = T1 * 0.69314718056f;
    }
    __syncthreads();
    if (tid < 5) {
        float a = 0.f;
        #pragma unroll
        for (int j = 0; j < 8; ++j) a += S[tid*8 + j];
        g_red[tid * NCHAN + ch] = a;
    }
    __threadfence();
    __syncthreads();
    if (tid == 0) s_last = (atomicAdd(&g_cnt, 1u) == (unsigned)(gridDim.x - 1));
    __syncthreads();
    if (!s_last) return;

    // ======================= HEAD (last block only) =======================
    __threadfence();

    for (int i = tid; i < 512; i += 256) ((float4*)(S+OFF_FC1W))[i] = ((const float4*)fc1_w)[i];
    for (int i = tid; i < 512; i += 256) ((float4*)(S+OFF_FC2W))[i] = ((const float4*)fc2_w)[i];
    for (int i = tid; i < 64;  i += 256) ((float4*)(S+OFF_C1W))[i]  = ((const float4*)cls1_w)[i];
    for (int i = tid; i < 160; i += 256) ((float4*)(S+OFF_C2W))[i]  = ((const float4*)cls2_w)[i];
    if (tid < 32)  S[OFF_F1B + tid] = fc1_b[tid];
    if (tid < 64)  S[OFF_F2B + tid] = fc2_b[tid];
    if (tid < 128) S[OFF_C1B + tid] = cls1_b[tid];
    if (tid < 5)   S[OFF_C2B + tid] = cls2_b[tid];
    for (int i = tid; i < NCHAN; i += 256) {       // z transposed z_T[c][b]
        int c = i >> 5, b = i & 31;
        S[OFF_Z + i] = __ldcg(&g_red[b * CH + c]) * (1.f / 65536.f);
    }
    __syncthreads();

    // h_T[j][b] = relu(z @ fc1_w^T + b)
    for (int i = tid; i < BATCH * 32; i += 256) {
        int j = i >> 5, b = i & 31;
        float acc = S[OFF_F1B + j];
        const float* wr = S + OFF_FC1W + j * CH;
        #pragma unroll
        for (int c = 0; c < CH; ++c) acc += S[OFF_Z + c*32 + b] * wr[c];
        S[OFF_H + j*32 + b] = fmaxf(acc, 0.f);
    }
    __syncthreads();

    // pre-softmax logits
    for (int i = tid; i < NCHAN; i += 256) {
        int c = i >> 5, b = i & 31;
        float acc = S[OFF_F2B + c];
        const float* wr = S + OFF_FC2W + c * 32;
        #pragma unroll
        for (int j = 0; j < 32; ++j) acc += S[OFF_H + j*32 + b] * wr[j];
        S[OFF_WSM + b*CH + c] = acc;
    }
    __syncthreads();

    // softmax per row
    for (int b = wrp; b < BATCH; b += 8) {
        float v0 = S[OFF_WSM + b*CH + lane];
        float v1 = S[OFF_WSM + b*CH + 32 + lane];
        float m = fmaxf(v0, v1);
        #pragma unroll
        for (int o = 16; o; o >>= 1) m = fmaxf(m, __shfl_xor_sync(0xffffffffu, m, o));
        float e0 = __expf(v0 - m), e1 = __expf(v1 - m);
        float s = e0 + e1;
        #pragma unroll
        for (int o = 16; o; o >>= 1) s += __shfl_xor_sync(0xffffffffu, s, o);
        float inv = 1.f / s;
        S[OFF_WSM + b*CH + lane]      = e0 * inv;
        S[OFF_WSM + b*CH + 32 + lane] = e1 * inv;
    }
    __syncthreads();

    // entropy closed form, write w
    for (int i = tid; i < NCHAN; i += 256) {
        float wv = S[OFF_WSM + i];
        out[BATCH*5 + i] = wv;
        float s0v = __ldcg(&g_red[1*NCHAN + i]);
        float t0v = __ldcg(&g_red[2*NCHAN + i]);
        float s1v = __ldcg(&g_red[3*NCHAN + i]);
        float t1v = __ldcg(&g_red[4*NCHAN + i]);
        float lw = __logf(wv);
        float a0 = wv * s0v, s0 = a0 + 1e-12f;
        float e0 = (a0 / s0) * (__logf(s0) - lw) - wv * t0v / s0;
        float a1 = wv * s1v, s1 = a1 + 1e-12f;
        float e1 = (a1 / s1) * (__logf(s1) - lw) - wv * t1v / s1;
        S[OFF_FC1W + i] = e0 * wv;
        S[OFF_FC2W + i] = e1 * wv;
    }
    __syncthreads();

    if (tid < BATCH * 2) {
        int b = tid >> 1, k = tid & 1;
        const float* cs = S + (k == 0 ? OFF_FC1W : OFF_FC2W) + b*CH;
        float acc = 0.f, ws = 0.f;
        #pragma unroll
        for (int c = 0; c < CH; ++c) { acc += cs[c]; ws += S[OFF_WSM + b*CH + c]; }
        float fv = acc / (ws + 1e-6f);
        S[OFF_FBUF + tid] = fv;
        out[BATCH*5 + NCHAN + tid] = fv;
    }
    __syncthreads();

    for (int i = tid; i < BATCH * 128; i += 256) {
        int b = i >> 7, j = i & 127;
        float mv = S[OFF_FBUF + 2*b] * S[OFF_C1W + 2*j]
                 + S[OFF_FBUF + 2*b + 1] * S[OFF_C1W + 2*j + 1]
                 + S[OFF_C1B + j];
        S[OFF_Z + i] = fmaxf(mv, 0.f);
    }
    __syncthreads();

    for (int i = tid; i < BATCH * 5; i += 256) {
        int b = i / 5, n = i - b * 5;
        float acc = S[OFF_C2B + n];
        const float* wr = S + OFF_C2W + n * 128;
        const float* mr = S + OFF_Z + b * 128;
        #pragma unroll
        for (int j = 0; j < 128; ++j) acc += mr[j] * wr[j];
        out[i] = acc;
    }
    if (tid == 0) g_cnt = 0;
}

extern "C" void kernel_launch(void* const* d_in, const int* in_sizes, int n_in,
                              void* d_out, int out_size) {
    const float* x      = (const float*)d_in[0];
    const float* fc1_w  = (const float*)d_in[1];
    const float* fc1_b  = (const float*)d_in[2];
    const float* fc2_w  = (const float*)d_in[3];
    const float* fc2_b  = (const float*)d_in[4];
    const float* cls1_w = (const float*)d_in[5];
    const float* cls1_b = (const float*)d_in[6];
    const float* cls2_w = (const float*)d_in[7];
    const float* cls2_b = (const float*)d_in[8];
    float* out = (float*)d_out;

    topo_fused_kernel<<<NCHAN, 256>>>(x, fc1_w, fc1_b, fc2_w, fc2_b,
                                      cls1_w, cls1_b, cls2_w, cls2_b, out);
}

// round 5
// speedup vs baseline: 2.5087x; 1.0636x over previous
#include <cuda_runtime.h>
#include <math.h>

#define BATCH 32
#define CH    64
#define HH    256
#define WW    256
#define NCHAN 2048

__device__ float g_red[5 * NCHAN];   // [0]=sum(x) [1]=S0 [2]=T0 [3]=S1 [4]=T1
__device__ unsigned int g_cnt = 0;

// ---- shared memory layout (floats) ----
#define OFF_FC1W 0
#define OFF_FC2W 2048
#define OFF_Z    4096
#define OFF_H    6144
#define OFF_WSM  7168
#define OFF_C1W  9216
#define OFF_C2W  9472
#define OFF_F1B  10112
#define OFF_F2B  10144
#define OFF_C1B  10208
#define OFF_C2B  10336
#define OFF_FBUF 10344
#define SMEM_FLOATS 10416

__device__ __forceinline__ void load8(const float* __restrict__ p, float* __restrict__ v) {
    float4 a = *(const float4*)p;
    float4 b = *(const float4*)(p + 4);
    v[0]=a.x; v[1]=a.y; v[2]=a.z; v[3]=a.w;
    v[4]=b.x; v[5]=b.y; v[6]=b.z; v[7]=b.w;
}

// Phase-P step: cur = v[P] (row r), next = v[(P+1)%3] (row r+1),
// prefetch row r+2 into v[(P+2)%3]. prx/prn = pair max/min over rows (r-1, r).
// Finalizes output row r; advances pair to (r, r+1). No register copies.
template<int P>
__device__ __forceinline__ void topo_step(
    const float* __restrict__ pf, bool eL, bool eR,
    float (&v)[3][8], float (&prx)[8], float (&prn)[8],
    float& zacc, float& S0, float& T0, float& S1, float& T1)
{
    constexpr int C = P;
    constexpr int N = (P + 1) % 3;
    constexpr int F = (P + 2) % 3;
    load8(pf, v[F]);

    const float* cur = v[C];
    const float* nx  = v[N];

    // vertical 3-row results for edge columns first (feed shuffles early)
    float vx7 = fmaxf(prx[7], nx[7]);
    float vn7 = fminf(prn[7], nx[7]);
    float vx0 = fmaxf(prx[0], nx[0]);
    float vn0 = fminf(prn[0], nx[0]);

    float Lxr = __shfl_up_sync(0xffffffffu, vx7, 1);
    float Lnr = __shfl_up_sync(0xffffffffu, vn7, 1);
    float Rxr = __shfl_down_sync(0xffffffffu, vx0, 1);
    float Rnr = __shfl_down_sync(0xffffffffu, vn0, 1);
    float ax = eL ? -INFINITY : Lxr;
    float an = eL ?  INFINITY : Lnr;
    float Rx = eR ? -INFINITY : Rxr;
    float Rn = eR ?  INFINITY : Rnr;

    float bx = vx0, bn = vn0;
    #pragma unroll
    for (int i = 0; i < 8; ++i) {
        float cx = (i < 7) ? fmaxf(prx[i+1], nx[i+1]) : Rx;
        float cn = (i < 7) ? fminf(prn[i+1], nx[i+1]) : Rn;
        float mx = fmaxf(ax, fmaxf(bx, cx));
        float mn = fminf(an, fminf(bn, cn));
        float y  = cur[i];
        zacc += y;
        float l0 = mx - y;
        float l1 = y - mn;
        S0 += l0; S1 += l1;
        T0 += l0 * __log2f(l0 + 1e-35f);
        T1 += l1 * __log2f(l1 + 1e-35f);
        ax = bx; bx = cx;
        an = bn; bn = cn;
    }
    #pragma unroll
    for (int i = 0; i < 8; ++i) {
        prx[i] = fmaxf(cur[i], nx[i]);
        prn[i] = fminf(cur[i], nx[i]);
    }
}

__global__ __launch_bounds__(256, 4)
void topo_fused_kernel(const float* __restrict__ x,
                       const float* __restrict__ fc1_w, const float* __restrict__ fc1_b,
                       const float* __restrict__ fc2_w, const float* __restrict__ fc2_b,
                       const float* __restrict__ cls1_w, const float* __restrict__ cls1_b,
                       const float* __restrict__ cls2_w, const float* __restrict__ cls2_b,
                       float* __restrict__ out)
{
    __shared__ __align__(16) float S[SMEM_FLOATS];
    __shared__ int s_last;

    const int ch   = blockIdx.x;
    const int tid  = threadIdx.x;
    const int wrp  = tid >> 5;
    const int lane = tid & 31;
    const bool eL = (lane == 0), eR = (lane == 31);
    const float* __restrict__ base = x + (size_t)ch * (HH * WW) + lane * 8;

    const int r0 = wrp * 32;                   // output rows r0 .. r0+31
    const int ra = (r0 == 0) ? 0 : (r0 - 1);

    float v[3][8], prx[8], prn[8];
    float zacc = 0.f, S0 = 0.f, T0 = 0.f, S1 = 0.f, T1 = 0.f;

    {
        float vp[8];
        load8(base + ra * WW, vp);             // row r0-1 (clamped)
        load8(base + r0 * WW, v[0]);           // cur  = row r0
        load8(base + (r0 + 1) * WW, v[1]);     // next = row r0+1
        #pragma unroll
        for (int i = 0; i < 8; ++i) {
            prx[i] = fmaxf(vp[i], v[0][i]);
            prn[i] = fminf(vp[i], v[0][i]);
        }
    }

    // Main loop: 30 uniform steps (loads rows r0+2 .. r0+31, never OOB).
    const float* p = base + (r0 + 2) * WW;
    #pragma unroll 1
    for (int g = 0; g < 10; ++g) {
        topo_step<0>(p,          eL, eR, v, prx, prn, zacc, S0, T0, S1, T1);
        topo_step<1>(p + WW,     eL, eR, v, prx, prn, zacc, S0, T0, S1, T1);
        topo_step<2>(p + 2*WW,   eL, eR, v, prx, prn, zacc, S0, T0, S1, T1);
        p += 3 * WW;
    }
    // Tail: out rows r0+30, r0+31; loads clamp to row 255 (warp 7 only).
    {
        const float* p30 = base + ((r0 + 32 > 255) ? 255 : (r0 + 32)) * WW;
        const float* p31 = base + ((r0 + 33 > 255) ? 255 : (r0 + 33)) * WW;
        topo_step<0>(p30, eL, eR, v, prx, prn, zacc, S0, T0, S1, T1);
        topo_step<1>(p31, eL, eR, v, prx, prn, zacc, S0, T0, S1, T1);
    }

    // warp reduce 5 accumulators
    #pragma unroll
    for (int o = 16; o; o >>= 1) {
        zacc += __shfl_down_sync(0xffffffffu, zacc, o);
        S0   += __shfl_down_sync(0xffffffffu, S0,   o);
        T0   += __shfl_down_sync(0xffffffffu, T0,   o);
        S1   += __shfl_down_sync(0xffffffffu, S1,   o);
        T1   += __shfl_down_sync(0xffffffffu, T1,   o);
    }
    if (lane == 0) {
        S[0*8 + wrp] = zacc;
        S[1*8 + wrp] = S0;
        S[2*8 + wrp] = T0 * 0.69314718056f;    // log2 -> ln
        S[3*8 + wrp] = S1;
        S[4*8 + wrp] = T1 * 0.69314718056f;
    }
    __syncthreads();
    if (tid < 5) {
        float a = 0.f;
        #pragma unroll
        for (int j = 0; j < 8; ++j) a += S[tid*8 + j];
        g_red[tid * NCHAN + ch] = a;
    }
    __threadfence();
    __syncthreads();
    if (tid == 0) s_last = (atomicAdd(&g_cnt, 1u) == (unsigned)(gridDim.x - 1));
    __syncthreads();
    if (!s_last) return;

    // ======================= HEAD (last block only) =======================
    __threadfence();

    for (int i = tid; i < 512; i += 256) ((float4*)(S+OFF_FC1W))[i] = ((const float4*)fc1_w)[i];
    for (int i = tid; i < 512; i += 256) ((float4*)(S+OFF_FC2W))[i] = ((const float4*)fc2_w)[i];
    for (int i = tid; i < 64;  i += 256) ((float4*)(S+OFF_C1W))[i]  = ((const float4*)cls1_w)[i];
    for (int i = tid; i < 160; i += 256) ((float4*)(S+OFF_C2W))[i]  = ((const float4*)cls2_w)[i];
    if (tid < 32)  S[OFF_F1B + tid] = fc1_b[tid];
    if (tid < 64)  S[OFF_F2B + tid] = fc2_b[tid];
    if (tid < 128) S[OFF_C1B + tid] = cls1_b[tid];
    if (tid < 5)   S[OFF_C2B + tid] = cls2_b[tid];
    for (int i = tid; i < NCHAN; i += 256) {       // z transposed z_T[c][b]
        int c = i >> 5, b = i & 31;
        S[OFF_Z + i] = __ldcg(&g_red[b * CH + c]) * (1.f / 65536.f);
    }
    __syncthreads();

    // h_T[j][b] = relu(z @ fc1_w^T + b)
    for (int i = tid; i < BATCH * 32; i += 256) {
        int j = i >> 5, b = i & 31;
        float acc = S[OFF_F1B + j];
        const float* wr = S + OFF_FC1W + j * CH;
        #pragma unroll
        for (int c = 0; c < CH; ++c) acc += S[OFF_Z + c*32 + b] * wr[c];
        S[OFF_H + j*32 + b] = fmaxf(acc, 0.f);
    }
    __syncthreads();

    // pre-softmax logits
    for (int i = tid; i < NCHAN; i += 256) {
        int c = i >> 5, b = i & 31;
        float acc = S[OFF_F2B + c];
        const float* wr = S + OFF_FC2W + c * 32;
        #pragma unroll
        for (int j = 0; j < 32; ++j) acc += S[OFF_H + j*32 + b] * wr[j];
        S[OFF_WSM + b*CH + c] = acc;
    }
    __syncthreads();

    // softmax per row
    for (int b = wrp; b < BATCH; b += 8) {
        float v0 = S[OFF_WSM + b*CH + lane];
        float v1 = S[OFF_WSM + b*CH + 32 + lane];
        float m = fmaxf(v0, v1);
        #pragma unroll
        for (int o = 16; o; o >>= 1) m = fmaxf(m, __shfl_xor_sync(0xffffffffu, m, o));
        float e0 = __expf(v0 - m), e1 = __expf(v1 - m);
        float s = e0 + e1;
        #pragma unroll
        for (int o = 16; o; o >>= 1) s += __shfl_xor_sync(0xffffffffu, s, o);
        float inv = 1.f / s;
        S[OFF_WSM + b*CH + lane]      = e0 * inv;
        S[OFF_WSM + b*CH + 32 + lane] = e1 * inv;
    }
    __syncthreads();

    // entropy closed form, write w
    for (int i = tid; i < NCHAN; i += 256) {
        float wv = S[OFF_WSM + i];
        out[BATCH*5 + i] = wv;
        float s0v = __ldcg(&g_red[1*NCHAN + i]);
        float t0v = __ldcg(&g_red[2*NCHAN + i]);
        float s1v = __ldcg(&g_red[3*NCHAN + i]);
        float t1v = __ldcg(&g_red[4*NCHAN + i]);
        float lw = __logf(wv);
        float a0 = wv * s0v, s0 = a0 + 1e-12f;
        float e0 = (a0 / s0) * (__logf(s0) - lw) - wv * t0v / s0;
        float a1 = wv * s1v, s1 = a1 + 1e-12f;
        float e1 = (a1 / s1) * (__logf(s1) - lw) - wv * t1v / s1;
        S[OFF_FC1W + i] = e0 * wv;
        S[OFF_FC2W + i] = e1 * wv;
    }
    __syncthreads();

    if (tid < BATCH * 2) {
        int b = tid >> 1, k = tid & 1;
        const float* cs = S + (k == 0 ? OFF_FC1W : OFF_FC2W) + b*CH;
        float acc = 0.f, ws = 0.f;
        #pragma unroll
        for (int c = 0; c < CH; ++c) { acc += cs[c]; ws += S[OFF_WSM + b*CH + c]; }
        float fv = acc / (ws + 1e-6f);
        S[OFF_FBUF + tid] = fv;
        out[BATCH*5 + NCHAN + tid] = fv;
    }
    __syncthreads();

    for (int i = tid; i < BATCH * 128; i += 256) {
        int b = i >> 7, j = i & 127;
        float mv = S[OFF_FBUF + 2*b] * S[OFF_C1W + 2*j]
                 + S[OFF_FBUF + 2*b + 1] * S[OFF_C1W + 2*j + 1]
                 + S[OFF_C1B + j];
        S[OFF_Z + i] = fmaxf(mv, 0.f);
    }
    __syncthreads();

    for (int i = tid; i < BATCH * 5; i += 256) {
        int b = i / 5, n = i - b * 5;
        float acc = S[OFF_C2B + n];
        const float* wr = S + OFF_C2W + n * 128;
        const float* mr = S + OFF_Z + b * 128;
        #pragma unroll
        for (int j = 0; j < 128; ++j) acc += mr[j] * wr[j];
        out[i] = acc;
    }
    if (tid == 0) g_cnt = 0;
}

extern "C" void kernel_launch(void* const* d_in, const int* in_sizes, int n_in,
                              void* d_out, int out_size) {
    const float* x      = (const float*)d_in[0];
    const float* fc1_w  = (const float*)d_in[1];
    const float* fc1_b  = (const float*)d_in[2];
    const float* fc2_w  = (const float*)d_in[3];
    const float* fc2_b  = (const float*)d_in[4];
    const float* cls1_w = (const float*)d_in[5];
    const float* cls1_b = (const float*)d_in[6];
    const float* cls2_w = (const float*)d_in[7];
    const float* cls2_b = (const float*)d_in[8];
    float* out = (float*)d_out;

    topo_fused_kernel<<<NCHAN, 256>>>(x, fc1_w, fc1_b, fc2_w, fc2_b,
                                      cls1_w, cls1_b, cls2_w, cls2_b, out);
}

// round 6
// speedup vs baseline: 2.5715x; 1.0250x over previous
#include <cuda_runtime.h>
#include <math.h>

#define BATCH 32
#define CH    64
#define HH    256
#define WW    256
#define NCHAN 2048

__device__ float g_red[5 * NCHAN];   // [0]=sum(x) [1]=S0 [2]=T0 [3]=S1 [4]=T1
__device__ unsigned int g_cnt = 0;

// ---- shared memory layout (floats) ----
#define OFF_FC1W 0
#define OFF_FC2W 2048
#define OFF_Z    4096
#define OFF_H    6144
#define OFF_WSM  7168
#define OFF_C1W  9216
#define OFF_C2W  9472
#define OFF_F1B  10112
#define OFF_F2B  10144
#define OFF_C1B  10208
#define OFF_C2B  10336
#define OFF_FBUF 10344
#define SMEM_FLOATS 10416

// packed f32x2 helpers (Blackwell FADD2/FFMA2 via PTX)
#define PACK2(d, lo, hi)  asm("mov.b64 %0, {%1, %2};" : "=l"(d) : "f"(lo), "f"(hi))
#define UNPK2(lo, hi, s)  asm("mov.b64 {%0, %1}, %2;" : "=f"(lo), "=f"(hi) : "l"(s))
#define ADDX2(d, a, b)    asm("add.rn.f32x2 %0, %1, %2;" : "=l"(d) : "l"(a), "l"(b))
#define FMAX2(d, a, b, c) asm("fma.rn.f32x2 %0, %1, %2, %3;" : "=l"(d) : "l"(a), "l"(b), "l"(c))

__device__ __forceinline__ void load8(const float* __restrict__ p, float* __restrict__ v) {
    float4 a = *(const float4*)p;
    float4 b = *(const float4*)(p + 4);
    v[0]=a.x; v[1]=a.y; v[2]=a.z; v[3]=a.w;
    v[4]=b.x; v[5]=b.y; v[6]=b.z; v[7]=b.w;
}

// Phase-P step: cur = v[P] (row r), next = v[(P+1)%3] (row r+1),
// prefetch row r+2 into v[(P+2)%3]. prx/prn = pair max/min over rows (r-1, r).
template<int P>
__device__ __forceinline__ void topo_step(
    const float* __restrict__ pf, bool eL, bool eR,
    float (&v)[3][8], float (&prx)[8], float (&prn)[8],
    unsigned long long& Z01, unsigned long long& S01, unsigned long long& T01,
    unsigned long long eps2)
{
    constexpr int C = P;
    constexpr int N = (P + 1) % 3;
    constexpr int F = (P + 2) % 3;
    load8(pf, v[F]);

    const float* cur = v[C];
    const float* nx  = v[N];

    // vertical 3-row results for edge columns first (feed shuffles early)
    float vx7 = fmaxf(prx[7], nx[7]);
    float vn7 = fminf(prn[7], nx[7]);
    float vx0 = fmaxf(prx[0], nx[0]);
    float vn0 = fminf(prn[0], nx[0]);

    float Lxr = __shfl_up_sync(0xffffffffu, vx7, 1);
    float Lnr = __shfl_up_sync(0xffffffffu, vn7, 1);
    float Rxr = __shfl_down_sync(0xffffffffu, vx0, 1);
    float Rnr = __shfl_down_sync(0xffffffffu, vn0, 1);
    float ax = eL ? -INFINITY : Lxr;
    float an = eL ?  INFINITY : Lnr;
    float Rx = eR ? -INFINITY : Rxr;
    float Rn = eR ?  INFINITY : Rnr;

    float bx = vx0, bn = vn0;
    #pragma unroll
    for (int i = 0; i < 8; ++i) {
        float cx = (i < 7) ? fmaxf(prx[i+1], nx[i+1]) : Rx;
        float cn = (i < 7) ? fminf(prn[i+1], nx[i+1]) : Rn;
        float mx = fmaxf(ax, fmaxf(bx, cx));
        float mn = fminf(an, fminf(bn, cn));
        float y  = cur[i];
        float l0 = mx - y;
        float l1 = y - mn;
        unsigned long long l01, le01, lg01;
        PACK2(l01, l0, l1);
        ADDX2(le01, l01, eps2);            // (l0+eps, l1+eps)
        float le0, le1;
        UNPK2(le0, le1, le01);
        float lg0 = __log2f(le0);
        float lg1 = __log2f(le1);
        PACK2(lg01, lg0, lg1);
        ADDX2(S01, S01, l01);              // (S0,S1) += (l0,l1)
        FMAX2(T01, l01, lg01, T01);        // (T0,T1) += (l0,l1)*(lg0,lg1)
        ax = bx; bx = cx;
        an = bn; bn = cn;
    }
    // zacc over cur row: float4-aligned register pairs
    #pragma unroll
    for (int j = 0; j < 4; ++j) {
        unsigned long long y01;
        PACK2(y01, cur[2*j], cur[2*j+1]);
        ADDX2(Z01, Z01, y01);
    }
    #pragma unroll
    for (int i = 0; i < 8; ++i) {
        prx[i] = fmaxf(cur[i], nx[i]);
        prn[i] = fminf(cur[i], nx[i]);
    }
}

__global__ __launch_bounds__(256, 4)
void topo_fused_kernel(const float* __restrict__ x,
                       const float* __restrict__ fc1_w, const float* __restrict__ fc1_b,
                       const float* __restrict__ fc2_w, const float* __restrict__ fc2_b,
                       const float* __restrict__ cls1_w, const float* __restrict__ cls1_b,
                       const float* __restrict__ cls2_w, const float* __restrict__ cls2_b,
                       float* __restrict__ out)
{
    __shared__ __align__(16) float S[SMEM_FLOATS];
    __shared__ int s_last;

    const int ch   = blockIdx.x;
    const int tid  = threadIdx.x;
    const int wrp  = tid >> 5;
    const int lane = tid & 31;
    const bool eL = (lane == 0), eR = (lane == 31);
    const float* __restrict__ base = x + (size_t)ch * (HH * WW) + lane * 8;

    const int r0 = wrp * 32;                   // output rows r0 .. r0+31
    const int ra = (r0 == 0) ? 0 : (r0 - 1);

    float v[3][8], prx[8], prn[8];
    unsigned long long Z01 = 0, S01 = 0, T01 = 0, eps2;
    {
        float e = 1e-35f;
        PACK2(eps2, e, e);
    }

    {
        float vp[8];
        load8(base + ra * WW, vp);             // row r0-1 (clamped)
        load8(base + r0 * WW, v[0]);           // cur  = row r0
        load8(base + (r0 + 1) * WW, v[1]);     // next = row r0+1
        #pragma unroll
        for (int i = 0; i < 8; ++i) {
            prx[i] = fmaxf(vp[i], v[0][i]);
            prn[i] = fminf(vp[i], v[0][i]);
        }
    }

    // Main loop: 30 uniform steps (loads rows r0+2 .. r0+31, never OOB).
    const float* p = base + (r0 + 2) * WW;
    #pragma unroll 1
    for (int g = 0; g < 10; ++g) {
        topo_step<0>(p,        eL, eR, v, prx, prn, Z01, S01, T01, eps2);
        topo_step<1>(p + WW,   eL, eR, v, prx, prn, Z01, S01, T01, eps2);
        topo_step<2>(p + 2*WW, eL, eR, v, prx, prn, Z01, S01, T01, eps2);
        p += 3 * WW;
    }
    // Tail: out rows r0+30, r0+31; loads clamp to row 255 (warp 7 only).
    {
        const float* p30 = base + ((r0 + 32 > 255) ? 255 : (r0 + 32)) * WW;
        const float* p31 = base + ((r0 + 33 > 255) ? 255 : (r0 + 33)) * WW;
        topo_step<0>(p30, eL, eR, v, prx, prn, Z01, S01, T01, eps2);
        topo_step<1>(p31, eL, eR, v, prx, prn, Z01, S01, T01, eps2);
    }

    float za, zb, S0, S1, T0, T1;
    UNPK2(za, zb, Z01);
    UNPK2(S0, S1, S01);
    UNPK2(T0, T1, T01);
    float zacc = za + zb;

    // warp reduce 5 accumulators
    #pragma unroll
    for (int o = 16; o; o >>= 1) {
        zacc += __shfl_down_sync(0xffffffffu, zacc, o);
        S0   += __shfl_down_sync(0xffffffffu, S0,   o);
        T0   += __shfl_down_sync(0xffffffffu, T0,   o);
        S1   += __shfl_down_sync(0xffffffffu, S1,   o);
        T1   += __shfl_down_sync(0xffffffffu, T1,   o);
    }
    if (lane == 0) {
        S[0*8 + wrp] = zacc;
        S[1*8 + wrp] = S0;
        S[2*8 + wrp] = T0 * 0.69314718056f;    // log2 -> ln
        S[3*8 + wrp] = S1;
        S[4*8 + wrp] = T1 * 0.69314718056f;
    }
    __syncthreads();
    if (tid < 5) {
        float a = 0.f;
        #pragma unroll
        for (int j = 0; j < 8; ++j) a += S[tid*8 + j];
        g_red[tid * NCHAN + ch] = a;
    }
    __threadfence();
    __syncthreads();
    if (tid == 0) s_last = (atomicAdd(&g_cnt, 1u) == (unsigned)(gridDim.x - 1));
    __syncthreads();
    if (!s_last) return;

    // ======================= HEAD (last block only) =======================
    __threadfence();

    for (int i = tid; i < 512; i += 256) ((float4*)(S+OFF_FC1W))[i] = ((const float4*)fc1_w)[i];
    for (int i = tid; i < 512; i += 256) ((float4*)(S+OFF_FC2W))[i] = ((const float4*)fc2_w)[i];
    for (int i = tid; i < 64;  i += 256) ((float4*)(S+OFF_C1W))[i]  = ((const float4*)cls1_w)[i];
    for (int i = tid; i < 160; i += 256) ((float4*)(S+OFF_C2W))[i]  = ((const float4*)cls2_w)[i];
    if (tid < 32)  S[OFF_F1B + tid] = fc1_b[tid];
    if (tid < 64)  S[OFF_F2B + tid] = fc2_b[tid];
    if (tid < 128) S[OFF_C1B + tid] = cls1_b[tid];
    if (tid < 5)   S[OFF_C2B + tid] = cls2_b[tid];
    for (int i = tid; i < NCHAN; i += 256) {       // z transposed z_T[c][b]
        int c = i >> 5, b = i & 31;
        S[OFF_Z + i] = __ldcg(&g_red[b * CH + c]) * (1.f / 65536.f);
    }
    __syncthreads();

    // h_T[j][b] = relu(z @ fc1_w^T + b)
    for (int i = tid; i < BATCH * 32; i += 256) {
        int j = i >> 5, b = i & 31;
        float acc = S[OFF_F1B + j];
        const float* wr = S + OFF_FC1W + j * CH;
        #pragma unroll
        for (int c = 0; c < CH; ++c) acc += S[OFF_Z + c*32 + b] * wr[c];
        S[OFF_H + j*32 + b] = fmaxf(acc, 0.f);
    }
    __syncthreads();

    // pre-softmax logits
    for (int i = tid; i < NCHAN; i += 256) {
        int c = i >> 5, b = i & 31;
        float acc = S[OFF_F2B + c];
        const float* wr = S + OFF_FC2W + c * 32;
        #pragma unroll
        for (int j = 0; j < 32; ++j) acc += S[OFF_H + j*32 + b] * wr[j];
        S[OFF_WSM + b*CH + c] = acc;
    }
    __syncthreads();

    // softmax per row
    for (int b = wrp; b < BATCH; b += 8) {
        float v0 = S[OFF_WSM + b*CH + lane];
        float v1 = S[OFF_WSM + b*CH + 32 + lane];
        float m = fmaxf(v0, v1);
        #pragma unroll
        for (int o = 16; o; o >>= 1) m = fmaxf(m, __shfl_xor_sync(0xffffffffu, m, o));
        float e0 = __expf(v0 - m), e1 = __expf(v1 - m);
        float s = e0 + e1;
        #pragma unroll
        for (int o = 16; o; o >>= 1) s += __shfl_xor_sync(0xffffffffu, s, o);
        float inv = 1.f / s;
        S[OFF_WSM + b*CH + lane]      = e0 * inv;
        S[OFF_WSM + b*CH + 32 + lane] = e1 * inv;
    }
    __syncthreads();

    // entropy closed form, write w
    for (int i = tid; i < NCHAN; i += 256) {
        float wv = S[OFF_WSM + i];
        out[BATCH*5 + i] = wv;
        float s0v = __ldcg(&g_red[1*NCHAN + i]);
        float t0v = __ldcg(&g_red[2*NCHAN + i]);
        float s1v = __ldcg(&g_red[3*NCHAN + i]);
        float t1v = __ldcg(&g_red[4*NCHAN + i]);
        float lw = __logf(wv);
        float a0 = wv * s0v, s0 = a0 + 1e-12f;
        float e0 = (a0 / s0) * (__logf(s0) - lw) - wv * t0v / s0;
        float a1 = wv * s1v, s1 = a1 + 1e-12f;
        float e1 = (a1 / s1) * (__logf(s1) - lw) - wv * t1v / s1;
        S[OFF_FC1W + i] = e0 * wv;
        S[OFF_FC2W + i] = e1 * wv;
    }
    __syncthreads();

    if (tid < BATCH * 2) {
        int b = tid >> 1, k = tid & 1;
        const float* cs = S + (k == 0 ? OFF_FC1W : OFF_FC2W) + b*CH;
        float acc = 0.f, ws = 0.f;
        #pragma unroll
        for (int c = 0; c < CH; ++c) { acc += cs[c]; ws += S[OFF_WSM + b*CH + c]; }
        float fv = acc / (ws + 1e-6f);
        S[OFF_FBUF + tid] = fv;
        out[BATCH*5 + NCHAN + tid] = fv;
    }
    __syncthreads();

    for (int i = tid; i < BATCH * 128; i += 256) {
        int b = i >> 7, j = i & 127;
        float mv = S[OFF_FBUF + 2*b] * S[OFF_C1W + 2*j]
                 + S[OFF_FBUF + 2*b + 1] * S[OFF_C1W + 2*j + 1]
                 + S[OFF_C1B + j];
        S[OFF_Z + i] = fmaxf(mv, 0.f);
    }
    __syncthreads();

    for (int i = tid; i < BATCH * 5; i += 256) {
        int b = i / 5, n = i - b * 5;
        float acc = S[OFF_C2B + n];
        const float* wr = S + OFF_C2W + n * 128;
        const float* mr = S + OFF_Z + b * 128;
        #pragma unroll
        for (int j = 0; j < 128; ++j) acc += mr[j] * wr[j];
        out[i] = acc;
    }
    if (tid == 0) g_cnt = 0;
}

extern "C" void kernel_launch(void* const* d_in, const int* in_sizes, int n_in,
                              void* d_out, int out_size) {
    const float* x      = (const float*)d_in[0];
    const float* fc1_w  = (const float*)d_in[1];
    const float* fc1_b  = (const float*)d_in[2];
    const float* fc2_w  = (const float*)d_in[3];
    const float* fc2_b  = (const float*)d_in[4];
    const float* cls1_w = (const float*)d_in[5];
    const float* cls1_b = (const float*)d_in[6];
    const float* cls2_w = (const float*)d_in[7];
    const float* cls2_b = (const float*)d_in[8];
    float* out = (float*)d_out;

    topo_fused_kernel<<<NCHAN, 256>>>(x, fc1_w, fc1_b, fc2_w, fc2_b,
                                      cls1_w, cls1_b, cls2_w, cls2_b, out);
}